// round 1
// baseline (speedup 1.0000x reference)
#include <cuda_runtime.h>

#define BB 8192
#define DD 64
#define KK 32
#define HID 16

#define KG 8        // k per block (one k per warp)
#define BT 128      // b per block (4 per lane)
#define NT 256      // threads per block
#define XPITCH 132  // padded row stride for transposed x in smem (floats)

// -------- device scratch (no allocations allowed) --------
__device__ float g_wpack[KK * DD * 32];  // per (k,d): [0:16)=A2, [16:32)=t
__device__ float g_tL[KK * DD];          // linear coefficient per (k,d)
__device__ float g_tCkd[KK * DD];        // constant per (k,d) (incl. ib2)
__device__ float g_Ck[KK];               // sum_d of g_tCkd
__device__ float g_oPack[KK * 32];       // outer net: A2 / t
__device__ float g_oL[KK];
__device__ float g_oC[KK];

// ---------------------------------------------------------
// Precompute: rewrite w2*relu(w1*x+b1) as A2*max(x,t) + L*x + C
//   w1>0: A2=w1*w2, t=-b1/w1, C+=w2*b1
//   w1<0: A2=-w1*w2, t=-b1/w1, L+=w1*w2   (constant cancels exactly)
//   w1=0: constant w2*relu(b1)
// ---------------------------------------------------------
__global__ void prep_inner(const float* __restrict__ iw1, const float* __restrict__ ib1,
                           const float* __restrict__ iw2, const float* __restrict__ ib2) {
    int kd = blockIdx.x * blockDim.x + threadIdx.x;
    if (kd >= KK * DD) return;
    const float* w1 = iw1 + kd * HID;
    const float* b1 = ib1 + kd * HID;
    const float* w2 = iw2 + kd * HID;
    float L = 0.f, C = ib2[kd];
    float* wp = g_wpack + kd * 32;
#pragma unroll
    for (int h = 0; h < HID; h++) {
        float a = w1[h], b = b1[h], c = w2[h];
        float A2, t;
        if (a > 0.f)      { A2 =  a * c; t = -b / a; C += c * b; }
        else if (a < 0.f) { A2 = -a * c; t = -b / a; L += a * c; }
        else              { A2 = 0.f;    t = 0.f;    C += c * fmaxf(b, 0.f); }
        wp[h]      = A2;
        wp[16 + h] = t;
    }
    g_tL[kd]   = L;
    g_tCkd[kd] = C;
}

__global__ void prep_outer(const float* __restrict__ ow1, const float* __restrict__ ob1,
                           const float* __restrict__ ow2, const float* __restrict__ ob2) {
    int k = threadIdx.x;
    if (k >= KK) return;
    float s = 0.f;
    for (int d = 0; d < DD; d++) s += g_tCkd[k * DD + d];
    g_Ck[k] = s;
    float L = 0.f, C = ob2[k];
    float* op = g_oPack + k * 32;
#pragma unroll
    for (int h = 0; h < HID; h++) {
        float a = ow1[k * HID + h], b = ob1[k * HID + h], c = ow2[k * HID + h];
        float A2, t;
        if (a > 0.f)      { A2 =  a * c; t = -b / a; C += c * b; }
        else if (a < 0.f) { A2 = -a * c; t = -b / a; L += a * c; }
        else              { A2 = 0.f;    t = 0.f;    C += c * fmaxf(b, 0.f); }
        op[h]      = A2;
        op[16 + h] = t;
    }
    g_oL[k] = L;
    g_oC[k] = C;
}

// ---------------------------------------------------------
// Main kernel: warp = fixed k, lanes carry 4 b's each.
// Inner per (b,k,d): 16 FMNMX (alu pipe) + 17 FFMA (fma pipe).
// ---------------------------------------------------------
__device__ __forceinline__ float kan_step(float xx, float acc, float Ld,
                                          const float4 wa[4], const float4 wt[4]) {
    acc = fmaf(Ld, xx, acc);
#pragma unroll
    for (int q = 0; q < 4; q++) {
        acc = fmaf(wa[q].x, fmaxf(xx, wt[q].x), acc);
        acc = fmaf(wa[q].y, fmaxf(xx, wt[q].y), acc);
        acc = fmaf(wa[q].z, fmaxf(xx, wt[q].z), acc);
        acc = fmaf(wa[q].w, fmaxf(xx, wt[q].w), acc);
    }
    return acc;
}

__global__ void __launch_bounds__(NT, 2)
kan_main(const float* __restrict__ x, float* __restrict__ out) {
    extern __shared__ float sm[];
    float* sw  = sm;                       // KG*DD*32 = 16384 floats
    float* sL  = sw  + KG * DD * 32;       // KG*DD   = 512
    float* sxT = sL  + KG * DD;            // DD*XPITCH = 8448
    float* sCk = sxT + DD * XPITCH;        // KG
    float* sop = sCk + KG;                 // KG*32
    float* soL = sop + KG * 32;            // KG
    float* soC = soL + KG;                 // KG

    const int t  = threadIdx.x;
    const int w  = t >> 5;
    const int l  = t & 31;
    const int k0 = blockIdx.y * KG;
    const int b0 = blockIdx.x * BT;

    // stage weights (coalesced, 16 float4 per thread)
    {
        const float4* gw  = (const float4*)(g_wpack + k0 * DD * 32);
        float4*       swv = (float4*)sw;
#pragma unroll
        for (int i = 0; i < (KG * DD * 32 / 4) / NT; i++)
            swv[t + i * NT] = gw[t + i * NT];
    }
    for (int i = t; i < KG * DD; i += NT) sL[i] = g_tL[k0 * DD + i];

    // stage x transposed: sxT[d][b]
    {
        const float4* gx = (const float4*)(x + (long)b0 * DD);
#pragma unroll
        for (int it = 0; it < (BT * DD / 4) / NT; it++) {
            int c   = t + it * NT;
            int row = c >> 4;       // b within tile
            int dc  = c & 15;       // float4 index within row
            float4 v = gx[c];
            int d = dc * 4;
            sxT[(d + 0) * XPITCH + row] = v.x;
            sxT[(d + 1) * XPITCH + row] = v.y;
            sxT[(d + 2) * XPITCH + row] = v.z;
            sxT[(d + 3) * XPITCH + row] = v.w;
        }
    }
    if (t < KG) { sCk[t] = g_Ck[k0 + t]; soL[t] = g_oL[k0 + t]; soC[t] = g_oC[k0 + t]; }
    for (int i = t; i < KG * 32; i += NT) sop[i] = g_oPack[k0 * 32 + i];
    __syncthreads();

    float acc0 = 0.f, acc1 = 0.f, acc2 = 0.f, acc3 = 0.f;
    const float* wbase = sw + w * DD * 32;
    const float* lbase = sL + w * DD;

#pragma unroll 2
    for (int d = 0; d < DD; d++) {
        const float4* wp = (const float4*)(wbase + d * 32);
        float4 wa[4], wt[4];
#pragma unroll
        for (int q = 0; q < 4; q++) wa[q] = wp[q];
#pragma unroll
        for (int q = 0; q < 4; q++) wt[q] = wp[4 + q];
        float  Ld = lbase[d];
        float4 xv = *(const float4*)(sxT + d * XPITCH + (l << 2));
        acc0 = kan_step(xv.x, acc0, Ld, wa, wt);
        acc1 = kan_step(xv.y, acc1, Ld, wa, wt);
        acc2 = kan_step(xv.z, acc2, Ld, wa, wt);
        acc3 = kan_step(xv.w, acc3, Ld, wa, wt);
    }

    // outer net (same transform), then store
    const int k   = k0 + w;
    const float Ck  = sCk[w];
    const float oLk = soL[w];
    const float oCk = soC[w];
    float oA[16], oT[16];
#pragma unroll
    for (int h = 0; h < 16; h++) { oA[h] = sop[w * 32 + h]; oT[h] = sop[w * 32 + 16 + h]; }

    float accs[4] = {acc0, acc1, acc2, acc3};
#pragma unroll
    for (int j = 0; j < 4; j++) {
        float s = accs[j] + Ck;
        float r = fmaf(oLk, s, oCk);
#pragma unroll
        for (int h = 0; h < 16; h++)
            r = fmaf(oA[h], fmaxf(s, oT[h]), r);
        out[(long)(b0 + 4 * l + j) * KK + k] = r;
    }
}

// ---------------------------------------------------------
extern "C" void kernel_launch(void* const* d_in, const int* in_sizes, int n_in,
                              void* d_out, int out_size) {
    const float* x   = (const float*)d_in[0];
    const float* iw1 = (const float*)d_in[1];
    const float* ib1 = (const float*)d_in[2];
    const float* iw2 = (const float*)d_in[3];
    const float* ib2 = (const float*)d_in[4];
    const float* ow1 = (const float*)d_in[5];
    const float* ob1 = (const float*)d_in[6];
    const float* ow2 = (const float*)d_in[7];
    const float* ob2 = (const float*)d_in[8];
    float* out = (float*)d_out;

    const int smem = (KG * DD * 32 + KG * DD + DD * XPITCH + KG + KG * 32 + 2 * KG) * 4;
    cudaFuncSetAttribute(kan_main, cudaFuncAttributeMaxDynamicSharedMemorySize, smem);

    prep_inner<<<(KK * DD + 127) / 128, 128>>>(iw1, ib1, iw2, ib2);
    prep_outer<<<1, 32>>>(ow1, ob1, ow2, ob2);

    dim3 grid(BB / BT, KK / KG);
    kan_main<<<grid, NT, smem>>>(x, out);
}

// round 2
// speedup vs baseline: 1.0863x; 1.0863x over previous
#include <cuda_runtime.h>

#define BB 8192
#define DD 64
#define KK 32
#define HID 16

#define KG 8        // k per block (one k per warp)
#define BT 128      // b per block (4 per lane)
#define NT 256      // threads per block
#define XPITCH 132  // padded row stride for transposed x in smem (floats)

// smem layout (floats)
#define SW_SZ   (KG * DD * 32)   // 16384 : per (k,d): [0:16)=A2, [16:32)=t
#define SL_SZ   (KG * DD)        // 512   : linear coeff per (k,d)
#define SC_SZ   (KG * DD)        // 512   : constant per (k,d)
#define SXT_SZ  (DD * XPITCH)    // 8448  : transposed x tile (reused as out tile)
#define SOP_SZ  (KG * 32)        // 256   : outer A2/t
#define SMEM_FLOATS (SW_SZ + SL_SZ + SC_SZ + SXT_SZ + KG + SOP_SZ + KG + KG)

// ---------------------------------------------------------
// Fused kernel: per-block prep (weights -> piecewise-linear form) + main eval.
// Identity: w2*relu(w1*x+b1) == A2*max(x,t) + L*x + C with
//   w1>0: A2= w1*w2, t=-b1/w1, C+=w2*b1
//   w1<0: A2=-w1*w2, t=-b1/w1, L+=w1*w2
//   w1=0: C += w2*relu(b1)
// ---------------------------------------------------------
__device__ __forceinline__ float kan_step(float xx, float acc, float Ld,
                                          const float4 wa[4], const float4 wt[4]) {
    acc = fmaf(Ld, xx, acc);
#pragma unroll
    for (int q = 0; q < 4; q++) {
        acc = fmaf(wa[q].x, fmaxf(xx, wt[q].x), acc);
        acc = fmaf(wa[q].y, fmaxf(xx, wt[q].y), acc);
        acc = fmaf(wa[q].z, fmaxf(xx, wt[q].z), acc);
        acc = fmaf(wa[q].w, fmaxf(xx, wt[q].w), acc);
    }
    return acc;
}

__global__ void __launch_bounds__(NT, 2)
kan_fused(const float* __restrict__ x,
          const float* __restrict__ iw1, const float* __restrict__ ib1,
          const float* __restrict__ iw2, const float* __restrict__ ib2,
          const float* __restrict__ ow1, const float* __restrict__ ob1,
          const float* __restrict__ ow2, const float* __restrict__ ob2,
          float* __restrict__ out) {
    extern __shared__ float sm[];
    float* sw  = sm;                 // SW_SZ
    float* sL  = sw  + SW_SZ;        // SL_SZ
    float* sC  = sL  + SL_SZ;        // SC_SZ
    float* sxT = sC  + SC_SZ;        // SXT_SZ (x tile; later reused as out tile)
    float* sCk = sxT + SXT_SZ;       // KG
    float* sop = sCk + KG;           // SOP_SZ
    float* soL = sop + SOP_SZ;       // KG
    float* soC = soL + KG;           // KG

    const int t  = threadIdx.x;
    const int w  = t >> 5;
    const int l  = t & 31;
    const int k0 = blockIdx.y * KG;
    const int b0 = blockIdx.x * BT;

    // ---------------- Phase A: per-block prep ----------------
    // Each thread transforms 2 (k,d) items (512 total).
#pragma unroll
    for (int it = 0; it < (KG * DD) / NT; it++) {
        int kd = t + it * NT;                    // local (k,d), k = kd>>6, d = kd&63
        long g = ((long)(k0 + (kd >> 6)) * DD + (kd & 63)) * HID;
        const float4* W1 = (const float4*)(iw1 + g);
        const float4* B1 = (const float4*)(ib1 + g);
        const float4* W2 = (const float4*)(iw2 + g);
        float L = 0.f, C = ib2[k0 * DD + kd];
        float4* swa = (float4*)(sw + kd * 32);
        float4* swt = swa + 4;
#pragma unroll
        for (int q = 0; q < 4; q++) {
            float4 av = W1[q], bv = B1[q], cv = W2[q];
            float4 A2v, tv;
            {
                float a = av.x, b = bv.x, c = cv.x, ac = a * c;
                if (a > 0.f)      { A2v.x = ac;  tv.x = __fdividef(-b, a); C += c * b; }
                else if (a < 0.f) { A2v.x = -ac; tv.x = __fdividef(-b, a); L += ac; }
                else              { A2v.x = 0.f; tv.x = 0.f; C += c * fmaxf(b, 0.f); }
            }
            {
                float a = av.y, b = bv.y, c = cv.y, ac = a * c;
                if (a > 0.f)      { A2v.y = ac;  tv.y = __fdividef(-b, a); C += c * b; }
                else if (a < 0.f) { A2v.y = -ac; tv.y = __fdividef(-b, a); L += ac; }
                else              { A2v.y = 0.f; tv.y = 0.f; C += c * fmaxf(b, 0.f); }
            }
            {
                float a = av.z, b = bv.z, c = cv.z, ac = a * c;
                if (a > 0.f)      { A2v.z = ac;  tv.z = __fdividef(-b, a); C += c * b; }
                else if (a < 0.f) { A2v.z = -ac; tv.z = __fdividef(-b, a); L += ac; }
                else              { A2v.z = 0.f; tv.z = 0.f; C += c * fmaxf(b, 0.f); }
            }
            {
                float a = av.w, b = bv.w, c = cv.w, ac = a * c;
                if (a > 0.f)      { A2v.w = ac;  tv.w = __fdividef(-b, a); C += c * b; }
                else if (a < 0.f) { A2v.w = -ac; tv.w = __fdividef(-b, a); L += ac; }
                else              { A2v.w = 0.f; tv.w = 0.f; C += c * fmaxf(b, 0.f); }
            }
            swa[q] = A2v;
            swt[q] = tv;
        }
        sL[kd] = L;
        sC[kd] = C;
    }

    // Outer-net prep: one thread per k (serial over HID, tiny).
    if (t < KG) {
        int k = k0 + t;
        float L = 0.f, C = ob2[k];
        float* op = sop + t * 32;
#pragma unroll
        for (int h = 0; h < HID; h++) {
            float a = ow1[k * HID + h], b = ob1[k * HID + h], c = ow2[k * HID + h];
            float ac = a * c, A2, tt;
            if (a > 0.f)      { A2 = ac;  tt = __fdividef(-b, a); C += c * b; }
            else if (a < 0.f) { A2 = -ac; tt = __fdividef(-b, a); L += ac; }
            else              { A2 = 0.f; tt = 0.f; C += c * fmaxf(b, 0.f); }
            op[h] = A2; op[16 + h] = tt;
        }
        soL[t] = L; soC[t] = C;
    }

    // Stage x transposed: sxT[d][b]
    {
        const float4* gx = (const float4*)(x + (long)b0 * DD);
#pragma unroll
        for (int it = 0; it < (BT * DD / 4) / NT; it++) {
            int c   = t + it * NT;
            int row = c >> 4;       // b within tile
            int dc  = c & 15;       // float4 index within row
            float4 v = gx[c];
            int d = dc * 4;
            sxT[(d + 0) * XPITCH + row] = v.x;
            sxT[(d + 1) * XPITCH + row] = v.y;
            sxT[(d + 2) * XPITCH + row] = v.z;
            sxT[(d + 3) * XPITCH + row] = v.w;
        }
    }
    __syncthreads();

    // Per-k constant = sum_d C (warp w reduces its 64 values)
    if (l < 32) {
        float v = sC[w * 64 + l] + sC[w * 64 + 32 + l];
#pragma unroll
        for (int o = 16; o > 0; o >>= 1) v += __shfl_xor_sync(0xffffffffu, v, o);
        if (l == 0) sCk[w] = v;
    }
    __syncthreads();

    // ---------------- Phase B: main evaluation ----------------
    float acc0 = 0.f, acc1 = 0.f, acc2 = 0.f, acc3 = 0.f;
    const float* wbase = sw + w * DD * 32;
    const float* lbase = sL + w * DD;

#pragma unroll 2
    for (int d = 0; d < DD; d++) {
        const float4* wp = (const float4*)(wbase + d * 32);
        float4 wa[4], wt[4];
#pragma unroll
        for (int q = 0; q < 4; q++) wa[q] = wp[q];
#pragma unroll
        for (int q = 0; q < 4; q++) wt[q] = wp[4 + q];
        float  Ld = lbase[d];
        float4 xv = *(const float4*)(sxT + d * XPITCH + (l << 2));
        acc0 = kan_step(xv.x, acc0, Ld, wa, wt);
        acc1 = kan_step(xv.y, acc1, Ld, wa, wt);
        acc2 = kan_step(xv.z, acc2, Ld, wa, wt);
        acc3 = kan_step(xv.w, acc3, Ld, wa, wt);
    }

    // Outer net (same piecewise-linear transform)
    const float Ck  = sCk[w];
    const float oLk = soL[w];
    const float oCk = soC[w];
    float oA[16], oT[16];
#pragma unroll
    for (int h = 0; h < 16; h++) { oA[h] = sop[w * 32 + h]; oT[h] = sop[w * 32 + 16 + h]; }

    float res[4];
    float accs[4] = {acc0, acc1, acc2, acc3};
#pragma unroll
    for (int j = 0; j < 4; j++) {
        float s = accs[j] + Ck;
        float r = fmaf(oLk, s, oCk);
#pragma unroll
        for (int h = 0; h < 16; h++)
            r = fmaf(oA[h], fmaxf(s, oT[h]), r);
        res[j] = r;
    }

    // ---------------- Phase C: coalesced store via smem transpose ----------------
    // Reuse sxT as out tile: sOut[b_local][w], pitch 9 to dodge bank conflicts.
    float* sOut = sxT;
    __syncthreads();
#pragma unroll
    for (int j = 0; j < 4; j++)
        sOut[(4 * l + j) * 9 + w] = res[j];
    __syncthreads();

    if (t < BT) {
        float v0 = sOut[t * 9 + 0], v1 = sOut[t * 9 + 1];
        float v2 = sOut[t * 9 + 2], v3 = sOut[t * 9 + 3];
        float v4 = sOut[t * 9 + 4], v5 = sOut[t * 9 + 5];
        float v6 = sOut[t * 9 + 6], v7 = sOut[t * 9 + 7];
        float4* o = (float4*)(out + (long)(b0 + t) * KK + k0);
        o[0] = make_float4(v0, v1, v2, v3);
        o[1] = make_float4(v4, v5, v6, v7);
    }
}

// ---------------------------------------------------------
extern "C" void kernel_launch(void* const* d_in, const int* in_sizes, int n_in,
                              void* d_out, int out_size) {
    const float* x   = (const float*)d_in[0];
    const float* iw1 = (const float*)d_in[1];
    const float* ib1 = (const float*)d_in[2];
    const float* iw2 = (const float*)d_in[3];
    const float* ib2 = (const float*)d_in[4];
    const float* ow1 = (const float*)d_in[5];
    const float* ob1 = (const float*)d_in[6];
    const float* ow2 = (const float*)d_in[7];
    const float* ob2 = (const float*)d_in[8];
    float* out = (float*)d_out;

    const int smem = SMEM_FLOATS * 4;
    cudaFuncSetAttribute(kan_fused, cudaFuncAttributeMaxDynamicSharedMemorySize, smem);

    dim3 grid(BB / BT, KK / KG);
    kan_fused<<<grid, NT, smem>>>(x, iw1, ib1, iw2, ib2, ow1, ob1, ow2, ob2, out);
}